// round 14
// baseline (speedup 1.0000x reference)
#include <cuda_runtime.h>
#include <cuda_bf16.h>

#define F_IN 1433
#define F1   16
#define F2   7
#define NMAX 50000
#define EMAX 1664000

// ---------------- scratch (no allocations allowed) ----------------
__device__ __align__(16) int   g_cnt [NMAX];
__device__ __align__(16) int   g_off [NMAX];
__device__ __align__(16) int   g_cur [NMAX];
__device__             int     g_total;
__device__ __align__(16) int   g_srcs[EMAX];
__device__ __align__(16) float g_dinv[NMAX];
__device__ __align__(16) float g_hs1 [NMAX * 16];
__device__ __align__(16) float g_hs2 [NMAX * 8];

// ---------------- CSR build ----------------
__global__ __launch_bounds__(256) void k_count(const int* __restrict__ ei, int E) {
    int i  = blockIdx.x * blockDim.x + threadIdx.x;
    int E4 = E >> 2;
    if (i < E4) {
        int4 d = ((const int4*)(ei + E))[i];
        atomicAdd(&g_cnt[d.x], 1);
        atomicAdd(&g_cnt[d.y], 1);
        atomicAdd(&g_cnt[d.z], 1);
        atomicAdd(&g_cnt[d.w], 1);
    }
    if (i == 0)
        for (int e = E4 << 2; e < E; ++e) atomicAdd(&g_cnt[ei[E + e]], 1);
}

__global__ __launch_bounds__(256) void k_alloc(int n) {
    int i    = blockIdx.x * blockDim.x + threadIdx.x;
    int lane = threadIdx.x & 31;
    int c    = (i < n) ? g_cnt[i] : 0;
    int incl = c;
    #pragma unroll
    for (int o = 1; o < 32; o <<= 1) {
        int v = __shfl_up_sync(0xffffffffu, incl, o);
        if (lane >= o) incl += v;
    }
    int tot  = __shfl_sync(0xffffffffu, incl, 31);
    int base = 0;
    if (lane == 31) base = atomicAdd(&g_total, tot);
    base = __shfl_sync(0xffffffffu, base, 31);
    if (i < n) {
        int off = base + incl - c;
        g_off[i] = off;
        g_cur[i] = off;
        g_dinv[i] = rsqrtf((float)(c + 1));
    }
}

__global__ __launch_bounds__(256) void k_fill(const int* __restrict__ ei, int E) {
    int i  = blockIdx.x * blockDim.x + threadIdx.x;
    int E4 = E >> 2;
    if (i < E4) {
        int4 s = ((const int4*)ei)[i];
        int4 d = ((const int4*)(ei + E))[i];
        int p0 = atomicAdd(&g_cur[d.x], 1);
        int p1 = atomicAdd(&g_cur[d.y], 1);
        int p2 = atomicAdd(&g_cur[d.z], 1);
        int p3 = atomicAdd(&g_cur[d.w], 1);
        g_srcs[p0] = s.x; g_srcs[p1] = s.y; g_srcs[p2] = s.z; g_srcs[p3] = s.w;
    }
    if (i == 0)
        for (int e = E4 << 2; e < E; ++e) {
            int p = atomicAdd(&g_cur[ei[E + e]], 1);
            g_srcs[p] = ei[e];
        }
}

// ---------------- GEMM1 v5: tensor cores (mma.sync bf16, hi/lo split) ----------------
// hs1 = (x @ W1) * dinv, fp32-accurate via 3-term bf16 split.
// 256 thr, 192 rows/block (12 m16 tiles: warps 0-3 two tiles, 4-7 one),
// grid 261 -> single wave at 2 blocks/SM. W_T hi/lo in smem [n][k] stride 1448;
// x staged per 16-k chunk into [192][24] bf16 hi/lo tiles (bank-conflict-free).
#define G1_BLK   256
#define G1_RPB   192
#define G1_GRID  261          // ceil(50000/192)
#define WT_STR   1448         // bf16 stride per n-row (bank-distinct for ldmatrix)
#define XS_STR   24           // bf16 per x row (16 used)
#define XS_WSTR  12           // 32-bit words per x row
#define NCHUNK   90           // ceil(1433/16)

#define LDSM4(r0,r1,r2,r3,addr) \
    asm volatile("ldmatrix.sync.aligned.m8n8.x4.shared.b16 {%0,%1,%2,%3}, [%4];" \
        : "=r"(r0), "=r"(r1), "=r"(r2), "=r"(r3) : "r"(addr))
#define LDSM2(r0,r1,addr) \
    asm volatile("ldmatrix.sync.aligned.m8n8.x2.shared.b16 {%0,%1}, [%2];" \
        : "=r"(r0), "=r"(r1) : "r"(addr))
#define MMA_BF16(D,a0,a1,a2,a3,b0,b1) \
    asm volatile("mma.sync.aligned.m16n8k16.row.col.f32.bf16.bf16.f32 " \
        "{%0,%1,%2,%3}, {%4,%5,%6,%7}, {%8,%9}, {%0,%1,%2,%3};" \
        : "+f"(D[0]), "+f"(D[1]), "+f"(D[2]), "+f"(D[3]) \
        : "r"(a0), "r"(a1), "r"(a2), "r"(a3), "r"(b0), "r"(b1))

__device__ __forceinline__ unsigned smem_u32(const void* p) {
    unsigned a;
    asm("{ .reg .u64 t; cvta.to.shared.u64 t, %1; cvt.u32.u64 %0, t; }" : "=r"(a) : "l"(p));
    return a;
}

__global__ __launch_bounds__(G1_BLK, 2) void k_gemm1(const float* __restrict__ x,
                                                     const float* __restrict__ W1, int n)
{
    extern __shared__ unsigned short smem_b16[];
    unsigned short* wt  = smem_b16;                        // [2][16][WT_STR] hi,lo
    unsigned short* xsh = wt + 2 * 16 * WT_STR;            // [192][24]
    unsigned short* xsl = xsh + G1_RPB * XS_STR;

    const int tid  = threadIdx.x;
    const int lane = tid & 31;
    const int wid  = tid >> 5;

    // ---- build W_T hi/lo (coalesced W1 read, one-time) ----
    for (int i = tid; i < 16 * WT_STR; i += G1_BLK) {
        int k = i >> 4, nn = i & 15;
        float v = (i < F_IN * F1) ? W1[i] : 0.f;    // i == k*16+nn
        __nv_bfloat16 hb = __float2bfloat16(v);
        float res = v - __bfloat162float(hb);
        wt[nn * WT_STR + k]               = __bfloat16_as_ushort(hb);
        wt[16 * WT_STR + nn * WT_STR + k] = __bfloat16_as_ushort(__float2bfloat16(res));
    }

    // ---- per-lane ldmatrix addresses ----
    int arow = (lane & 7) + ((lane >> 3) & 1) * 8;
    int akof = ((lane >> 4) & 1) * 16;                     // bytes
    unsigned xsh_b = smem_u32(xsh), xsl_b = smem_u32(xsl);
    unsigned aoff0 = (unsigned)(((wid & 3) * 16 + ((wid >> 2) * 64) + arow) * XS_STR * 2 + akof);
    // tile map: warp w -> tile t0 = w (rows w*16), t1 = w+8 (w<4)
    unsigned ah0 = xsh_b + (unsigned)(((wid * 16) + arow) * XS_STR * 2 + akof);
    unsigned al0 = xsl_b + (unsigned)(((wid * 16) + arow) * XS_STR * 2 + akof);
    unsigned ah1 = xsh_b + (unsigned)((((wid + 8) * 16) + arow) * XS_STR * 2 + akof);
    unsigned al1 = xsl_b + (unsigned)((((wid + 8) * 16) + arow) * XS_STR * 2 + akof);
    (void)aoff0;

    unsigned wt_b = smem_u32(wt);
    int bn = lane & 7;
    int bk = ((lane >> 3) & 1) * 16;                        // bytes
    unsigned bh_addr[2], bl_addr[2];
    #pragma unroll
    for (int h = 0; h < 2; ++h) {
        bh_addr[h] = wt_b + (unsigned)(((bn + 8 * h) * WT_STR) * 2 + bk);
        bl_addr[h] = bh_addr[h] + 16 * WT_STR * 2;
    }

    const int row0 = blockIdx.x * G1_RPB;
    float acc[2][2][4];
    #pragma unroll
    for (int t = 0; t < 2; ++t)
        #pragma unroll
        for (int h = 0; h < 2; ++h)
            #pragma unroll
            for (int q = 0; q < 4; ++q) acc[t][h][q] = 0.f;

    const int srow = tid >> 3;     // 0..31
    const int skp  = tid & 7;      // k-pair
    __syncthreads();               // W_T ready

    for (int ch = 0; ch < NCHUNK; ++ch) {
        int k0 = ch * 16;
        // ---- stage x chunk (hi/lo bf16) ----
        #pragma unroll
        for (int it = 0; it < 6; ++it) {
            int r  = srow + 32 * it;
            int gr = row0 + r;
            int gk = k0 + 2 * skp;
            float v0 = 0.f, v1 = 0.f;
            if (gr < n) {
                const float* xp = x + (size_t)gr * F_IN + gk;
                if (gk + 1 < F_IN)      { v0 = xp[0]; v1 = xp[1]; }
                else if (gk < F_IN)     { v0 = xp[0]; }
            }
            unsigned ph, pl;
            asm("cvt.rn.bf16x2.f32 %0, %1, %2;" : "=r"(ph) : "f"(v1), "f"(v0));
            float r0 = v0 - __int_as_float(ph << 16);
            float r1 = v1 - __int_as_float(ph & 0xffff0000u);
            asm("cvt.rn.bf16x2.f32 %0, %1, %2;" : "=r"(pl) : "f"(r1), "f"(r0));
            ((unsigned*)xsh)[r * XS_WSTR + skp] = ph;
            ((unsigned*)xsl)[r * XS_WSTR + skp] = pl;
        }
        __syncthreads();
        // ---- B fragments for this chunk ----
        unsigned bh[2][2], bl[2][2];
        #pragma unroll
        for (int h = 0; h < 2; ++h) {
            LDSM2(bh[h][0], bh[h][1], bh_addr[h] + (unsigned)(ch * 32));
            LDSM2(bl[h][0], bl[h][1], bl_addr[h] + (unsigned)(ch * 32));
        }
        // ---- tile 0 ----
        {
            unsigned a0, a1, a2, a3, l0, l1, l2, l3;
            LDSM4(a0, a1, a2, a3, ah0);
            LDSM4(l0, l1, l2, l3, al0);
            #pragma unroll
            for (int h = 0; h < 2; ++h) {
                MMA_BF16(acc[0][h], a0, a1, a2, a3, bh[h][0], bh[h][1]);
                MMA_BF16(acc[0][h], l0, l1, l2, l3, bh[h][0], bh[h][1]);
                MMA_BF16(acc[0][h], a0, a1, a2, a3, bl[h][0], bl[h][1]);
            }
        }
        // ---- tile 1 (warps 0-3) ----
        if (wid < 4) {
            unsigned a0, a1, a2, a3, l0, l1, l2, l3;
            LDSM4(a0, a1, a2, a3, ah1);
            LDSM4(l0, l1, l2, l3, al1);
            #pragma unroll
            for (int h = 0; h < 2; ++h) {
                MMA_BF16(acc[1][h], a0, a1, a2, a3, bh[h][0], bh[h][1]);
                MMA_BF16(acc[1][h], l0, l1, l2, l3, bh[h][0], bh[h][1]);
                MMA_BF16(acc[1][h], a0, a1, a2, a3, bl[h][0], bl[h][1]);
            }
        }
        __syncthreads();           // chunk consumed; safe to restage
    }

    // ---- epilogue: scale by dinv, direct store ----
    #pragma unroll
    for (int t = 0; t < 2; ++t) {
        if (t == 1 && wid >= 4) break;
        int tile = t ? (wid + 8) : wid;
        int rA = row0 + tile * 16 + (lane >> 2);
        int rB = rA + 8;
        float diA = (rA < n) ? g_dinv[rA] : 0.f;
        float diB = (rB < n) ? g_dinv[rB] : 0.f;
        #pragma unroll
        for (int h = 0; h < 2; ++h) {
            int c = 2 * (lane & 3) + 8 * h;
            if (rA < n) {
                float2 o = make_float2(acc[t][h][0] * diA, acc[t][h][1] * diA);
                *(float2*)(g_hs1 + (size_t)rA * 16 + c) = o;
            }
            if (rB < n) {
                float2 o = make_float2(acc[t][h][2] * diB, acc[t][h][3] * diB);
                *(float2*)(g_hs1 + (size_t)rB * 16 + c) = o;
            }
        }
    }
}

// ---------------- gather L1 + bias/ReLU + layer2 GEMM (fused) ----------------
__global__ __launch_bounds__(256) void k_gather16(const float* __restrict__ b1,
                                                  const float* __restrict__ W2, int n) {
    __shared__ float w2s[F1 * F2];
    if (threadIdx.x < F1 * F2) w2s[threadIdx.x] = W2[threadIdx.x];
    __syncthreads();

    int wid  = threadIdx.x >> 5;
    int lane = threadIdx.x & 31;
    int d    = blockIdx.x * 8 + wid;
    if (d >= n) return;

    int base = g_off[d];
    int cnt  = g_cnt[d];
    int grp  = lane >> 2;
    int col  = lane & 3;

    float4 acc = make_float4(0.f, 0.f, 0.f, 0.f);
    for (int it = grp; it < cnt; it += 8) {
        int s = g_srcs[base + it];
        float4 v = ((const float4*)(g_hs1 + (size_t)s * 16))[col];
        acc.x += v.x; acc.y += v.y; acc.z += v.z; acc.w += v.w;
    }
    __syncwarp();
    #pragma unroll
    for (int o = 16; o >= 4; o >>= 1) {
        acc.x += __shfl_xor_sync(0xffffffffu, acc.x, o);
        acc.y += __shfl_xor_sync(0xffffffffu, acc.y, o);
        acc.z += __shfl_xor_sync(0xffffffffu, acc.z, o);
        acc.w += __shfl_xor_sync(0xffffffffu, acc.w, o);
    }
    float  di   = g_dinv[d];
    float4 self = ((const float4*)(g_hs1 + (size_t)d * 16))[col];
    float4 b    = __ldg((const float4*)b1 + col);
    float4 o;
    o.x = fmaxf(fmaf(di, acc.x + self.x, b.x), 0.f);
    o.y = fmaxf(fmaf(di, acc.y + self.y, b.y), 0.f);
    o.z = fmaxf(fmaf(di, acc.z + self.z, b.z), 0.f);
    o.w = fmaxf(fmaf(di, acc.w + self.w, b.w), 0.f);

    float a[F1];
    #pragma unroll
    for (int j = 0; j < F1; ++j) {
        float c;
        switch (j & 3) { case 0: c = o.x; break; case 1: c = o.y; break;
                         case 2: c = o.z; break; default: c = o.w; }
        a[j] = __shfl_sync(0xffffffffu, c, j >> 2);
    }
    if (lane < 8) {
        float v = 0.f;
        if (lane < 7) {
            float h = 0.f;
            #pragma unroll
            for (int j = 0; j < F1; ++j) h = fmaf(a[j], w2s[j * F2 + lane], h);
            v = h * di;
        }
        g_hs2[(size_t)d * 8 + lane] = v;
    }
}

// ---------------- gather L2 + bias + log_softmax (fused) ----------------
__global__ __launch_bounds__(256) void k_gather8f(const float* __restrict__ b2,
                                                  float* __restrict__ out, int n) {
    int wid  = threadIdx.x >> 5;
    int lane = threadIdx.x & 31;
    int d    = blockIdx.x * 8 + wid;
    if (d >= n) return;

    int base = g_off[d];
    int cnt  = g_cnt[d];
    int grp  = lane >> 1;
    int half = lane & 1;

    float4 acc = make_float4(0.f, 0.f, 0.f, 0.f);
    for (int it = grp; it < cnt; it += 16) {
        int s = g_srcs[base + it];
        float4 v = ((const float4*)(g_hs2 + (size_t)s * 8))[half];
        acc.x += v.x; acc.y += v.y; acc.z += v.z; acc.w += v.w;
    }
    __syncwarp();
    #pragma unroll
    for (int o = 16; o >= 2; o >>= 1) {
        acc.x += __shfl_down_sync(0xffffffffu, acc.x, o);
        acc.y += __shfl_down_sync(0xffffffffu, acc.y, o);
        acc.z += __shfl_down_sync(0xffffffffu, acc.z, o);
        acc.w += __shfl_down_sync(0xffffffffu, acc.w, o);
    }
    if (lane < 2) {
        float4 self = ((const float4*)(g_hs2 + (size_t)d * 8))[lane];
        acc.x += self.x; acc.y += self.y; acc.z += self.z; acc.w += self.w;
    }
    float hx = __shfl_sync(0xffffffffu, acc.x, 1);
    float hy = __shfl_sync(0xffffffffu, acc.y, 1);
    float hz = __shfl_sync(0xffffffffu, acc.z, 1);
    if (lane == 0) {
        float di = g_dinv[d];
        float v[7] = {acc.x, acc.y, acc.z, acc.w, hx, hy, hz};
        #pragma unroll
        for (int k = 0; k < 7; ++k) v[k] = fmaf(di, v[k], __ldg(b2 + k));
        float m = v[0];
        #pragma unroll
        for (int k = 1; k < 7; ++k) m = fmaxf(m, v[k]);
        float s = 0.f;
        #pragma unroll
        for (int k = 0; k < 7; ++k) s += expf(v[k] - m);
        float l = m + logf(s);
        float* op = out + (size_t)d * 7;
        #pragma unroll
        for (int k = 0; k < 7; ++k) op[k] = v[k] - l;
    }
}

// ---------------- launch ----------------
extern "C" void kernel_launch(void* const* d_in, const int* in_sizes, int n_in,
                              void* d_out, int out_size)
{
    const float* x  = (const float*)d_in[0];
    const int*   ei = (const int*)d_in[1];     // int32 (JAX x64 disabled)
    const float* W1 = (const float*)d_in[2];
    const float* b1 = (const float*)d_in[3];
    const float* W2 = (const float*)d_in[4];
    const float* b2 = (const float*)d_in[5];

    int n = in_sizes[0] / F_IN;   // 50000
    int E = in_sizes[1] / 2;      // 1600000

    const int smem1 = (2 * 16 * WT_STR + 2 * G1_RPB * XS_STR) * 2;   // 111104 B
    cudaFuncSetAttribute(k_gemm1, cudaFuncAttributeMaxDynamicSharedMemorySize, smem1);

    void* p_cnt = 0; void* p_total = 0;
    cudaGetSymbolAddress(&p_cnt, g_cnt);
    cudaGetSymbolAddress(&p_total, g_total);

    int nb256 = (n + 255) / 256;
    int e4b   = ((E >> 2) + 255) / 256;
    int gwarp = (n + 7) / 8;

    cudaMemsetAsync(p_cnt, 0, NMAX * sizeof(int), 0);
    cudaMemsetAsync(p_total, 0, sizeof(int), 0);
    k_count   <<<e4b, 256>>>(ei, E);                   // 1
    k_alloc   <<<nb256, 256>>>(n);                     // 2
    k_fill    <<<e4b, 256>>>(ei, E);                   // 3
    k_gemm1   <<<G1_GRID, G1_BLK, smem1>>>(x, W1, n);  // 4 -> ncu sample
    k_gather16<<<gwarp, 256>>>(b1, W2, n);             // 5
    k_gather8f<<<gwarp, 256>>>(b2, (float*)d_out, n);  // 6
}

// round 17
// speedup vs baseline: 1.4179x; 1.4179x over previous
#include <cuda_runtime.h>
#include <cuda_bf16.h>

#define F_IN 1433
#define F1   16
#define F2   7
#define NMAX 50000
#define EMAX 1664000

// ---------------- scratch (no allocations allowed) ----------------
__device__ __align__(16) int   g_cnt [NMAX];
__device__ __align__(16) int   g_off [NMAX];
__device__ __align__(16) int   g_cur [NMAX];
__device__             int     g_total;
__device__ __align__(16) int   g_srcs[EMAX];
__device__ __align__(16) float g_dinv[NMAX];
__device__ __align__(16) float g_hs1 [NMAX * 16];
__device__ __align__(16) float g_hs2 [NMAX * 8];

// ---------------- CSR build ----------------
__global__ __launch_bounds__(256) void k_count(const int* __restrict__ ei, int E) {
    int i  = blockIdx.x * blockDim.x + threadIdx.x;
    int E4 = E >> 2;
    if (i < E4) {
        int4 d = ((const int4*)(ei + E))[i];
        atomicAdd(&g_cnt[d.x], 1);
        atomicAdd(&g_cnt[d.y], 1);
        atomicAdd(&g_cnt[d.z], 1);
        atomicAdd(&g_cnt[d.w], 1);
    }
    if (i == 0)
        for (int e = E4 << 2; e < E; ++e) atomicAdd(&g_cnt[ei[E + e]], 1);
}

__global__ __launch_bounds__(256) void k_alloc(int n) {
    int i    = blockIdx.x * blockDim.x + threadIdx.x;
    int lane = threadIdx.x & 31;
    int c    = (i < n) ? g_cnt[i] : 0;
    int incl = c;
    #pragma unroll
    for (int o = 1; o < 32; o <<= 1) {
        int v = __shfl_up_sync(0xffffffffu, incl, o);
        if (lane >= o) incl += v;
    }
    int tot  = __shfl_sync(0xffffffffu, incl, 31);
    int base = 0;
    if (lane == 31) base = atomicAdd(&g_total, tot);
    base = __shfl_sync(0xffffffffu, base, 31);
    if (i < n) {
        int off = base + incl - c;
        g_off[i] = off;
        g_cur[i] = off;
        g_dinv[i] = rsqrtf((float)(c + 1));
    }
}

__global__ __launch_bounds__(256) void k_fill(const int* __restrict__ ei, int E) {
    int i  = blockIdx.x * blockDim.x + threadIdx.x;
    int E4 = E >> 2;
    if (i < E4) {
        int4 s = ((const int4*)ei)[i];
        int4 d = ((const int4*)(ei + E))[i];
        int p0 = atomicAdd(&g_cur[d.x], 1);
        int p1 = atomicAdd(&g_cur[d.y], 1);
        int p2 = atomicAdd(&g_cur[d.z], 1);
        int p3 = atomicAdd(&g_cur[d.w], 1);
        g_srcs[p0] = s.x; g_srcs[p1] = s.y; g_srcs[p2] = s.z; g_srcs[p3] = s.w;
    }
    if (i == 0)
        for (int e = E4 << 2; e < E; ++e) {
            int p = atomicAdd(&g_cur[ei[E + e]], 1);
            g_srcs[p] = ei[e];
        }
}

// ---------------- GEMM1 v6b: mma.sync bf16 hi/lo, warp-private pipelined staging ----------------
// hs1 = (x @ W1) * dinv. 256 thr, 192 rows/block (12 m16 tiles; warps 0-3 two
// tiles, 4-7 one), grid 261. No __syncthreads in mainloop: warp-private smem
// staging tiles, register prefetch of chunk ch+1 overlaps LDSM+MMA of chunk ch.
// Row stride 12 words (48 B): 16B-aligned for ldmatrix (R15 bug: 40 B), and
// conflict-free per LDSM phase (12r mod 32 distinct for r=0..7).
#define G1_BLK   256
#define G1_RPB   192
#define G1_GRID  261
#define WT_STR   1448         // bf16 per n-row of W_T (bank-distinct for ldmatrix)
#define NCHUNK   90           // ceil(1433/16)
#define XT_W     12           // 32-bit words per staged row (8 used) -> 48 B, 16B-aligned
#define XT_HALF  192          // words per hi (or lo) tile = 16*12
#define XT_TILE  384          // words per tile (hi+lo)

#define LDSM4(r0,r1,r2,r3,addr) \
    asm volatile("ldmatrix.sync.aligned.m8n8.x4.shared.b16 {%0,%1,%2,%3}, [%4];" \
        : "=r"(r0), "=r"(r1), "=r"(r2), "=r"(r3) : "r"(addr))
#define LDSM2(r0,r1,addr) \
    asm volatile("ldmatrix.sync.aligned.m8n8.x2.shared.b16 {%0,%1}, [%2];" \
        : "=r"(r0), "=r"(r1) : "r"(addr))
#define MMA_BF16(D,a0,a1,a2,a3,b0,b1) \
    asm volatile("mma.sync.aligned.m16n8k16.row.col.f32.bf16.bf16.f32 " \
        "{%0,%1,%2,%3}, {%4,%5,%6,%7}, {%8,%9}, {%0,%1,%2,%3};" \
        : "+f"(D[0]), "+f"(D[1]), "+f"(D[2]), "+f"(D[3]) \
        : "r"(a0), "r"(a1), "r"(a2), "r"(a3), "r"(b0), "r"(b1))

__device__ __forceinline__ unsigned smem_u32(const void* p) {
    unsigned a;
    asm("{ .reg .u64 t; cvta.to.shared.u64 t, %1; cvt.u32.u64 %0, t; }" : "=r"(a) : "l"(p));
    return a;
}

__global__ __launch_bounds__(G1_BLK, 2) void k_gemm1(const float* __restrict__ x,
                                                     const float* __restrict__ W1, int n)
{
    extern __shared__ unsigned char smem_raw[];
    unsigned short* wt = (unsigned short*)smem_raw;                    // [2][16][WT_STR]
    unsigned*       xs = (unsigned*)(smem_raw + 2 * 16 * WT_STR * 2);  // [12][2][192] words

    const int tid  = threadIdx.x;
    const int lane = tid & 31;
    const int wid  = tid >> 5;
    const int row0 = blockIdx.x * G1_RPB;

    // ---- build W_T hi/lo (one-time, validated in R14) ----
    for (int i = tid; i < 16 * WT_STR; i += G1_BLK) {
        int k = i >> 4, nn = i & 15;
        float v = (i < F_IN * F1) ? W1[i] : 0.f;      // i == k*16+nn
        __nv_bfloat16 hb = __float2bfloat16(v);
        float res = v - __bfloat162float(hb);
        wt[nn * WT_STR + k]               = __bfloat16_as_ushort(hb);
        wt[16 * WT_STR + nn * WT_STR + k] = __bfloat16_as_ushort(__float2bfloat16(res));
    }

    // ---- per-warp tiles and lane coords ----
    const int ntile = (wid < 4) ? 2 : 1;
    int tiles[2] = {wid, wid + 8};
    const int sr  = lane >> 1;           // staged row 0..15
    const int sk8 = (lane & 1) * 8;      // k offset 0/8

    unsigned stsoff[2];
    int      grow[2];
    #pragma unroll
    for (int t = 0; t < 2; ++t) {
        stsoff[t] = (unsigned)(tiles[t] * XT_TILE + sr * XT_W + (lane & 1) * 4);
        grow[t]   = row0 + tiles[t] * 16 + sr;
    }

    // ldmatrix A addresses (fragment layout identical to validated R14)
    unsigned xs_b = smem_u32(xs);
    int arow = (lane & 7) + ((lane >> 3) & 1) * 8;
    int akof = ((lane >> 4) & 1) * 16;
    unsigned ah[2], al[2];
    #pragma unroll
    for (int t = 0; t < 2; ++t) {
        ah[t] = xs_b + (unsigned)(tiles[t] * XT_TILE * 4 + arow * (XT_W * 4) + akof);
        al[t] = ah[t] + XT_HALF * 4;
    }

    // W fragment addresses (unchanged)
    unsigned wt_b = smem_u32(wt);
    int bn = lane & 7;
    int bk = ((lane >> 3) & 1) * 16;
    unsigned bh_addr[2], bl_addr[2];
    #pragma unroll
    for (int h = 0; h < 2; ++h) {
        bh_addr[h] = wt_b + (unsigned)(((bn + 8 * h) * WT_STR) * 2 + bk);
        bl_addr[h] = bh_addr[h] + 16 * WT_STR * 2;
    }

    float acc[2][2][4];
    #pragma unroll
    for (int t = 0; t < 2; ++t)
        #pragma unroll
        for (int h = 0; h < 2; ++h)
            #pragma unroll
            for (int q = 0; q < 4; ++q) acc[t][h][q] = 0.f;

    // ---- prologue: load chunk 0 into registers ----
    float xr[2][8];
    #pragma unroll
    for (int t = 0; t < 2; ++t) {
        if (t >= ntile) break;
        int gr = grow[t];
        const float* xp = x + (size_t)gr * F_IN + sk8;
        #pragma unroll
        for (int j = 0; j < 8; ++j)
            xr[t][j] = (gr < n && (sk8 + j) < F_IN) ? xp[j] : 0.f;
    }

    __syncthreads();    // W_T ready (only block-wide barrier)

    for (int ch = 0; ch < NCHUNK; ++ch) {
        // ---- STS current chunk (convert to hi/lo bf16x2) ----
        #pragma unroll
        for (int t = 0; t < 2; ++t) {
            if (t >= ntile) break;
            unsigned* hw = xs + stsoff[t];
            unsigned* lw = hw + XT_HALF;
            #pragma unroll
            for (int j = 0; j < 4; ++j) {
                float v0 = xr[t][2 * j], v1 = xr[t][2 * j + 1];
                unsigned ph, pl;
                asm("cvt.rn.bf16x2.f32 %0, %1, %2;" : "=r"(ph) : "f"(v1), "f"(v0));
                float r0 = v0 - __int_as_float(ph << 16);
                float r1 = v1 - __int_as_float(ph & 0xffff0000u);
                asm("cvt.rn.bf16x2.f32 %0, %1, %2;" : "=r"(pl) : "f"(r1), "f"(r0));
                hw[j] = ph; lw[j] = pl;
            }
        }
        __syncwarp();
        // ---- prefetch chunk ch+1 (overlaps LDSM+MMA below) ----
        if (ch + 1 < NCHUNK) {
            int k0 = (ch + 1) * 16;
            #pragma unroll
            for (int t = 0; t < 2; ++t) {
                if (t >= ntile) break;
                int gr = grow[t];
                const float* xp = x + (size_t)gr * F_IN + k0 + sk8;
                #pragma unroll
                for (int j = 0; j < 8; ++j)
                    xr[t][j] = (gr < n && (k0 + sk8 + j) < F_IN) ? xp[j] : 0.f;
            }
        }
        // ---- W fragments for this chunk ----
        unsigned bh[2][2], bl[2][2];
        #pragma unroll
        for (int h = 0; h < 2; ++h) {
            LDSM2(bh[h][0], bh[h][1], bh_addr[h] + (unsigned)(ch * 32));
            LDSM2(bl[h][0], bl[h][1], bl_addr[h] + (unsigned)(ch * 32));
        }
        // ---- A fragments + MMA ----
        #pragma unroll
        for (int t = 0; t < 2; ++t) {
            if (t >= ntile) break;
            unsigned a0, a1, a2, a3, l0, l1, l2, l3;
            LDSM4(a0, a1, a2, a3, ah[t]);
            LDSM4(l0, l1, l2, l3, al[t]);
            #pragma unroll
            for (int h = 0; h < 2; ++h) {
                MMA_BF16(acc[t][h], a0, a1, a2, a3, bh[h][0], bh[h][1]);
                MMA_BF16(acc[t][h], l0, l1, l2, l3, bh[h][0], bh[h][1]);
                MMA_BF16(acc[t][h], a0, a1, a2, a3, bl[h][0], bl[h][1]);
            }
        }
        __syncwarp();   // LDSM reads done before next iteration's STS
    }

    // ---- epilogue: scale by dinv, direct store (layout validated in R14) ----
    #pragma unroll
    for (int t = 0; t < 2; ++t) {
        if (t >= ntile) break;
        int rA = row0 + tiles[t] * 16 + (lane >> 2);
        int rB = rA + 8;
        float diA = (rA < n) ? g_dinv[rA] : 0.f;
        float diB = (rB < n) ? g_dinv[rB] : 0.f;
        #pragma unroll
        for (int h = 0; h < 2; ++h) {
            int c = 2 * (lane & 3) + 8 * h;
            if (rA < n) {
                float2 o = make_float2(acc[t][h][0] * diA, acc[t][h][1] * diA);
                *(float2*)(g_hs1 + (size_t)rA * 16 + c) = o;
            }
            if (rB < n) {
                float2 o = make_float2(acc[t][h][2] * diB, acc[t][h][3] * diB);
                *(float2*)(g_hs1 + (size_t)rB * 16 + c) = o;
            }
        }
    }
}

// ---------------- gather L1 + bias/ReLU + layer2 GEMM (fused) ----------------
__global__ __launch_bounds__(256) void k_gather16(const float* __restrict__ b1,
                                                  const float* __restrict__ W2, int n) {
    __shared__ float w2s[F1 * F2];
    if (threadIdx.x < F1 * F2) w2s[threadIdx.x] = W2[threadIdx.x];
    __syncthreads();

    int wid  = threadIdx.x >> 5;
    int lane = threadIdx.x & 31;
    int d    = blockIdx.x * 8 + wid;
    if (d >= n) return;

    int base = g_off[d];
    int cnt  = g_cnt[d];
    int grp  = lane >> 2;
    int col  = lane & 3;

    float4 acc = make_float4(0.f, 0.f, 0.f, 0.f);
    for (int it = grp; it < cnt; it += 8) {
        int s = g_srcs[base + it];
        float4 v = ((const float4*)(g_hs1 + (size_t)s * 16))[col];
        acc.x += v.x; acc.y += v.y; acc.z += v.z; acc.w += v.w;
    }
    __syncwarp();
    #pragma unroll
    for (int o = 16; o >= 4; o >>= 1) {
        acc.x += __shfl_xor_sync(0xffffffffu, acc.x, o);
        acc.y += __shfl_xor_sync(0xffffffffu, acc.y, o);
        acc.z += __shfl_xor_sync(0xffffffffu, acc.z, o);
        acc.w += __shfl_xor_sync(0xffffffffu, acc.w, o);
    }
    float  di   = g_dinv[d];
    float4 self = ((const float4*)(g_hs1 + (size_t)d * 16))[col];
    float4 b    = __ldg((const float4*)b1 + col);
    float4 o;
    o.x = fmaxf(fmaf(di, acc.x + self.x, b.x), 0.f);
    o.y = fmaxf(fmaf(di, acc.y + self.y, b.y), 0.f);
    o.z = fmaxf(fmaf(di, acc.z + self.z, b.z), 0.f);
    o.w = fmaxf(fmaf(di, acc.w + self.w, b.w), 0.f);

    float a[F1];
    #pragma unroll
    for (int j = 0; j < F1; ++j) {
        float c;
        switch (j & 3) { case 0: c = o.x; break; case 1: c = o.y; break;
                         case 2: c = o.z; break; default: c = o.w; }
        a[j] = __shfl_sync(0xffffffffu, c, j >> 2);
    }
    if (lane < 8) {
        float v = 0.f;
        if (lane < 7) {
            float h = 0.f;
            #pragma unroll
            for (int j = 0; j < F1; ++j) h = fmaf(a[j], w2s[j * F2 + lane], h);
            v = h * di;
        }
        g_hs2[(size_t)d * 8 + lane] = v;
    }
}

// ---------------- gather L2 + bias + log_softmax (fused) ----------------
__global__ __launch_bounds__(256) void k_gather8f(const float* __restrict__ b2,
                                                  float* __restrict__ out, int n) {
    int wid  = threadIdx.x >> 5;
    int lane = threadIdx.x & 31;
    int d    = blockIdx.x * 8 + wid;
    if (d >= n) return;

    int base = g_off[d];
    int cnt  = g_cnt[d];
    int grp  = lane >> 1;
    int half = lane & 1;

    float4 acc = make_float4(0.f, 0.f, 0.f, 0.f);
    for (int it = grp; it < cnt; it += 16) {
        int s = g_srcs[base + it];
        float4 v = ((const float4*)(g_hs2 + (size_t)s * 8))[half];
        acc.x += v.x; acc.y += v.y; acc.z += v.z; acc.w += v.w;
    }
    __syncwarp();
    #pragma unroll
    for (int o = 16; o >= 2; o >>= 1) {
        acc.x += __shfl_down_sync(0xffffffffu, acc.x, o);
        acc.y += __shfl_down_sync(0xffffffffu, acc.y, o);
        acc.z += __shfl_down_sync(0xffffffffu, acc.z, o);
        acc.w += __shfl_down_sync(0xffffffffu, acc.w, o);
    }
    if (lane < 2) {
        float4 self = ((const float4*)(g_hs2 + (size_t)d * 8))[lane];
        acc.x += self.x; acc.y += self.y; acc.z += self.z; acc.w += self.w;
    }
    float hx = __shfl_sync(0xffffffffu, acc.x, 1);
    float hy = __shfl_sync(0xffffffffu, acc.y, 1);
    float hz = __shfl_sync(0xffffffffu, acc.z, 1);
    if (lane == 0) {
        float di = g_dinv[d];
        float v[7] = {acc.x, acc.y, acc.z, acc.w, hx, hy, hz};
        #pragma unroll
        for (int k = 0; k < 7; ++k) v[k] = fmaf(di, v[k], __ldg(b2 + k));
        float m = v[0];
        #pragma unroll
        for (int k = 1; k < 7; ++k) m = fmaxf(m, v[k]);
        float s = 0.f;
        #pragma unroll
        for (int k = 0; k < 7; ++k) s += expf(v[k] - m);
        float l = m + logf(s);
        float* op = out + (size_t)d * 7;
        #pragma unroll
        for (int k = 0; k < 7; ++k) op[k] = v[k] - l;
    }
}

// ---------------- launch ----------------
extern "C" void kernel_launch(void* const* d_in, const int* in_sizes, int n_in,
                              void* d_out, int out_size)
{
    const float* x  = (const float*)d_in[0];
    const int*   ei = (const int*)d_in[1];     // int32 (JAX x64 disabled)
    const float* W1 = (const float*)d_in[2];
    const float* b1 = (const float*)d_in[3];
    const float* W2 = (const float*)d_in[4];
    const float* b2 = (const float*)d_in[5];

    int n = in_sizes[0] / F_IN;   // 50000
    int E = in_sizes[1] / 2;      // 1600000

    const int smem1 = 2 * 16 * WT_STR * 2 + 12 * XT_TILE * 4;   // 92672 + 18432 = 111104 B
    cudaFuncSetAttribute(k_gemm1, cudaFuncAttributeMaxDynamicSharedMemorySize, smem1);

    void* p_cnt = 0; void* p_total = 0;
    cudaGetSymbolAddress(&p_cnt, g_cnt);
    cudaGetSymbolAddress(&p_total, g_total);

    int nb256 = (n + 255) / 256;
    int e4b   = ((E >> 2) + 255) / 256;
    int gwarp = (n + 7) / 8;

    cudaMemsetAsync(p_cnt, 0, NMAX * sizeof(int), 0);
    cudaMemsetAsync(p_total, 0, sizeof(int), 0);
    k_count   <<<e4b, 256>>>(ei, E);                   // 1
    k_alloc   <<<nb256, 256>>>(n);                     // 2
    k_fill    <<<e4b, 256>>>(ei, E);                   // 3
    k_gemm1   <<<G1_GRID, G1_BLK, smem1>>>(x, W1, n);  // 4 -> ncu sample
    k_gather16<<<gwarp, 256>>>(b1, W2, n);             // 5
    k_gather8f<<<gwarp, 256>>>(b2, (float*)d_out, n);  // 6
}